// round 1
// baseline (speedup 1.0000x reference)
#include <cuda_runtime.h>

#define HH 96
#define WW 96
#define HWN 9216
#define CN 256
#define BB 2
#define NOUT 648
#define NPAD 704
#define KBIG 2304

// ---------------- scratch (device globals; no allocation) ----------------
__device__ float g_qpre[BB * CN * HWN];      // pre-LN projected query
__device__ float g_qchw[BB * CN * HWN];      // LN'd query, CHW
__device__ float g_qhwc[BB * HWN * CN];      // LN'd query, HWC (for gathers)
__device__ float g_conv[BB * NOUT * HWN];    // offsets+masks conv output
__device__ float g_Wpack[KBIG * NPAD];       // packed conv weights [k][n]
__device__ float g_bpack[NPAD];
__device__ float g_WA[CN * CN];              // in_w transposed [k][n]
__device__ float g_sW[BB * 3 * CN * 9];      // LN'd support (deform weights)
__device__ float g_pool[BB * 6 * 128];       // max-pooled support
__device__ float g_sim[BB * 24 * HWN];       // similarity maps

// ---------------- packing ----------------
__global__ void pack_wa(const float* __restrict__ inw) {
    int idx = blockIdx.x * 256 + threadIdx.x;   // 65536
    int k = idx >> 8, n = idx & 255;
    g_WA[k * CN + n] = inw[n * CN + k];
}

__global__ void pack_big(const float* __restrict__ ow1, const float* __restrict__ mw1,
                         const float* __restrict__ ow2, const float* __restrict__ mw2,
                         const float* __restrict__ ow4, const float* __restrict__ mw4,
                         const float* __restrict__ ob1, const float* __restrict__ mb1,
                         const float* __restrict__ ob2, const float* __restrict__ mb2,
                         const float* __restrict__ ob4, const float* __restrict__ mb4) {
    int idx = blockIdx.x * 256 + threadIdx.x;
    if (idx < KBIG * NPAD) {
        int k = idx / NPAD, n = idx - (idx / NPAD) * NPAD;
        float v = 0.f;
        if (n < NOUT) {
            int d = n / 216, r = n - d * 216;
            const float* w = (r < 144) ? (d == 0 ? ow1 : d == 1 ? ow2 : ow4)
                                       : (d == 0 ? mw1 : d == 1 ? mw2 : mw4);
            int oc = (r < 144) ? r : r - 144;
            v = w[oc * KBIG + k];
        }
        g_Wpack[k * NPAD + n] = v;
    }
    if (idx < NPAD) {
        float v = 0.f;
        if (idx < NOUT) {
            int d = idx / 216, r = idx - d * 216;
            const float* bb = (r < 144) ? (d == 0 ? ob1 : d == 1 ? ob2 : ob4)
                                        : (d == 0 ? mb1 : d == 1 ? mb2 : mb4);
            v = bb[(r < 144) ? r : r - 144];
        }
        g_bpack[idx] = v;
    }
}

// ---------------- 1x1 in-projection GEMM (q) ----------------
// M=9216/batch (BM=128), N=256 (BN=64), K=256 (BK=16), 256 threads, 8x4 micro
__global__ void gemm_in(const float* __restrict__ x, const float* __restrict__ bias) {
    __shared__ __align__(16) float As[16 * 64];
    __shared__ __align__(16) float Bs[16 * 128];
    int b = blockIdx.z;
    int m0 = blockIdx.x * 128, n0 = blockIdx.y * 64;
    int tid = threadIdx.x;
    int tn = tid & 15, tm = tid >> 4;
    int kk_ld = tid >> 4, q = tid & 15;
    float acc[8][4];
#pragma unroll
    for (int j = 0; j < 8; j++)
#pragma unroll
        for (int i = 0; i < 4; i++) acc[j][i] = 0.f;
    const float* xb = x + (size_t)b * CN * HWN;
    for (int k0 = 0; k0 < 256; k0 += 16) {
        *(float4*)&As[kk_ld * 64 + q * 4] =
            *(const float4*)&g_WA[(k0 + kk_ld) * CN + n0 + q * 4];
        const float* src = &xb[(k0 + kk_ld) * HWN + m0 + q * 8];
        *(float4*)&Bs[kk_ld * 128 + q * 8]     = *(const float4*)&src[0];
        *(float4*)&Bs[kk_ld * 128 + q * 8 + 4] = *(const float4*)&src[4];
        __syncthreads();
#pragma unroll
        for (int kk = 0; kk < 16; kk++) {
            float4 a  = *(const float4*)&As[kk * 64 + tn * 4];
            float4 b0 = *(const float4*)&Bs[kk * 128 + tm * 8];
            float4 b1 = *(const float4*)&Bs[kk * 128 + tm * 8 + 4];
            float av[4] = {a.x, a.y, a.z, a.w};
            float bv[8] = {b0.x, b0.y, b0.z, b0.w, b1.x, b1.y, b1.z, b1.w};
#pragma unroll
            for (int j = 0; j < 8; j++)
#pragma unroll
                for (int i = 0; i < 4; i++) acc[j][i] += bv[j] * av[i];
        }
        __syncthreads();
    }
#pragma unroll
    for (int i = 0; i < 4; i++) {
        int n = n0 + tn * 4 + i;
        float bi = bias[n];
        float* dst = &g_qpre[((size_t)b * CN + n) * HWN + m0 + tm * 8];
#pragma unroll
        for (int j = 0; j < 8; j++) dst[j] = acc[j][i] + bi;
    }
}

// ---------------- fused 3x3 conv GEMM (offsets + masks, all 3 dilations) ----------------
__global__ void gemm_big() {
    __shared__ __align__(16) float As[16 * 64];
    __shared__ __align__(16) float Bs[16 * 128];
    int b = blockIdx.z;
    int m0 = blockIdx.x * 128, n0 = blockIdx.y * 64;
    int tid = threadIdx.x;
    int tn = tid & 15, tm = tid >> 4;
    int kk_ld = tid >> 4, q = tid & 15;
    int ybuf[8], xbuf[8];
#pragma unroll
    for (int j = 0; j < 8; j++) {
        int pm = m0 + q * 8 + j;
        ybuf[j] = pm / 96;
        xbuf[j] = pm - ybuf[j] * 96;
    }
    float acc[8][4];
#pragma unroll
    for (int j = 0; j < 8; j++)
#pragma unroll
        for (int i = 0; i < 4; i++) acc[j][i] = 0.f;
    const float* qb = g_qchw + (size_t)b * CN * HWN;
    for (int k0 = 0; k0 < KBIG; k0 += 16) {
        *(float4*)&As[kk_ld * 64 + q * 4] =
            *(const float4*)&g_Wpack[(size_t)(k0 + kk_ld) * NPAD + n0 + q * 4];
        int k = k0 + kk_ld;
        int c = k / 9;
        int tap = k - c * 9;
        int t3 = tap / 3;
        int dty = t3 - 1, dtx = (tap - t3 * 3) - 1;
        const float* src = qb + c * HWN;
#pragma unroll
        for (int j = 0; j < 8; j++) {
            int yy = ybuf[j] + dty, xx = xbuf[j] + dtx;
            float v = 0.f;
            if ((unsigned)yy < 96u && (unsigned)xx < 96u) v = __ldg(&src[yy * 96 + xx]);
            Bs[kk_ld * 128 + q * 8 + j] = v;
        }
        __syncthreads();
#pragma unroll
        for (int kk = 0; kk < 16; kk++) {
            float4 a  = *(const float4*)&As[kk * 64 + tn * 4];
            float4 b0 = *(const float4*)&Bs[kk * 128 + tm * 8];
            float4 b1 = *(const float4*)&Bs[kk * 128 + tm * 8 + 4];
            float av[4] = {a.x, a.y, a.z, a.w};
            float bv[8] = {b0.x, b0.y, b0.z, b0.w, b1.x, b1.y, b1.z, b1.w};
#pragma unroll
            for (int j = 0; j < 8; j++)
#pragma unroll
                for (int i = 0; i < 4; i++) acc[j][i] += bv[j] * av[i];
        }
        __syncthreads();
    }
#pragma unroll
    for (int i = 0; i < 4; i++) {
        int n = n0 + tn * 4 + i;
        if (n >= NOUT) continue;
        float bi = g_bpack[n];
        float* dst = &g_conv[((size_t)b * NOUT + n) * HWN + m0 + tm * 8];
#pragma unroll
        for (int j = 0; j < 8; j++) dst[j] = acc[j][i] + bi;
    }
}

// ---------------- channel LayerNorm (q) + CHW/HWC dual write ----------------
__global__ void ln_kernel(const float* __restrict__ gam, const float* __restrict__ bet) {
    __shared__ float tile[32 * 257];
    __shared__ float red1[8][32], red2[8][32];
    __shared__ float mus[32], rvs[32];
    int tid = threadIdx.x;
    int pl = tid & 31, cg = tid >> 5;
    int pg0 = blockIdx.x * 32;
    int pg = pg0 + pl;
    int b = pg / HWN;
    int p = pg - b * HWN;
    float s1 = 0.f, s2 = 0.f;
#pragma unroll
    for (int i = 0; i < 32; i++) {
        int c = cg * 32 + i;
        float v = g_qpre[((size_t)b * CN + c) * HWN + p];
        tile[pl * 257 + c] = v;
        s1 += v; s2 += v * v;
    }
    red1[cg][pl] = s1; red2[cg][pl] = s2;
    __syncthreads();
    if (tid < 32) {
        float a = 0.f, bb = 0.f;
#pragma unroll
        for (int j = 0; j < 8; j++) { a += red1[j][tid]; bb += red2[j][tid]; }
        float mu = a * (1.f / 256.f);
        float var = bb * (1.f / 256.f) - mu * mu;
        mus[tid] = mu;
        rvs[tid] = rsqrtf(var + 1e-5f);
    }
    __syncthreads();
    float mu = mus[pl], rv = rvs[pl];
#pragma unroll
    for (int i = 0; i < 32; i++) {
        int c = cg * 32 + i;
        float val = (tile[pl * 257 + c] - mu) * rv * gam[c] + bet[c];
        g_qchw[((size_t)b * CN + c) * HWN + p] = val;
        tile[pl * 257 + c] = val;
    }
    __syncthreads();
#pragma unroll
    for (int i = 0; i < 32; i++) {
        int idx = tid + i * 256;
        int pp = idx >> 8, c = idx & 255;
        g_qhwc[(size_t)(pg0 + pp) * 256 + c] = tile[pp * 257 + c];
    }
}

// ---------------- support path: 1x1 proj + LN + maxpool ----------------
__global__ void support_kernel(const float* __restrict__ sup, const float* __restrict__ inb,
                               const float* __restrict__ gam, const float* __restrict__ bet) {
    __shared__ float xs[2304];
    __shared__ float ys[2304];
    __shared__ float stats[18];
    int bid = blockIdx.x;
    int b = bid / 3, ex = bid - b * 3;
    int tid = threadIdx.x;
    const float* sp = sup + (size_t)(b * 3 + ex) * 2304;
    for (int i = tid; i < 2304; i += 256) xs[i] = sp[i];
    __syncthreads();
    float acc[9];
#pragma unroll
    for (int pos = 0; pos < 9; pos++) acc[pos] = inb[tid];
    for (int k = 0; k < 256; k++) {
        float w = g_WA[k * 256 + tid];
#pragma unroll
        for (int pos = 0; pos < 9; pos++) acc[pos] += w * xs[k * 9 + pos];
    }
#pragma unroll
    for (int pos = 0; pos < 9; pos++) ys[tid * 9 + pos] = acc[pos];
    __syncthreads();
    if (tid < 9) {
        float s1 = 0.f, s2 = 0.f;
        for (int c = 0; c < 256; c++) { float v = ys[c * 9 + tid]; s1 += v; s2 += v * v; }
        float mu = s1 * (1.f / 256.f);
        float var = s2 * (1.f / 256.f) - mu * mu;
        stats[tid] = mu;
        stats[9 + tid] = rsqrtf(var + 1e-5f);
    }
    __syncthreads();
    float mx = -1e30f;
    float g = gam[tid], be = bet[tid];
#pragma unroll
    for (int pos = 0; pos < 9; pos++) {
        float v = (acc[pos] - stats[pos]) * stats[9 + pos] * g + be;
        g_sW[((size_t)(b * 3 + ex) * 256 + tid) * 9 + pos] = v;
        mx = fmaxf(mx, v);
    }
    int r = ex * 2 + (tid >> 7);
    g_pool[(b * 6 + r) * 128 + (tid & 127)] = mx;
}

// ---------------- mask softmax over 72 channels per pixel (in-place) ----------------
__global__ void softmax_kernel() {
    int p = blockIdx.x * 256 + threadIdx.x;
    int dz = blockIdx.y, b = blockIdx.z;
    float* base = g_conv + ((size_t)(b * NOUT) + dz * 216 + 144) * HWN + p;
    float mx = -1e30f;
    for (int i = 0; i < 72; i++) mx = fmaxf(mx, base[(size_t)i * HWN]);
    float s = 0.f;
    for (int i = 0; i < 72; i++) {
        float e = expf(base[(size_t)i * HWN] - mx);
        base[(size_t)i * HWN] = e;
        s += e;
    }
    float inv = 1.f / s;
    for (int i = 0; i < 72; i++) base[(size_t)i * HWN] *= inv;
}

// ---------------- sim0 (pooled 1x1 grouped branch) ----------------
__global__ void sim0_kernel() {
    __shared__ __align__(16) float psh[6 * 128];
    int b = blockIdx.y;
    int tid = threadIdx.x;
    int lane8 = tid & 7, pl = tid >> 3;
    int pg = blockIdx.x * 32 + pl;
    for (int i = tid; i < 768; i += 256) psh[i] = g_pool[b * 768 + i];
    __syncthreads();
    const float* qrow = g_qhwc + ((size_t)b * HWN + pg) * CN;
    float acc[6];
#pragma unroll
    for (int r = 0; r < 6; r++) acc[r] = 0.f;
#pragma unroll
    for (int r = 0; r < 6; r++) {
        int g = (r >= 3) ? 1 : 0;
#pragma unroll
        for (int qq = 0; qq < 4; qq++) {
            int f = lane8 + qq * 8;
            float4 qv = *(const float4*)&qrow[g * 128 + f * 4];
            float4 pv = *(const float4*)&psh[r * 128 + f * 4];
            acc[r] += qv.x * pv.x + qv.y * pv.y + qv.z * pv.z + qv.w * pv.w;
        }
    }
#pragma unroll
    for (int r = 0; r < 6; r++) {
        acc[r] += __shfl_xor_sync(0xffffffffu, acc[r], 1);
        acc[r] += __shfl_xor_sync(0xffffffffu, acc[r], 2);
        acc[r] += __shfl_xor_sync(0xffffffffu, acc[r], 4);
    }
    if (lane8 == 0) {
#pragma unroll
        for (int r = 0; r < 6; r++)
            g_sim[((size_t)b * 24 + r) * HWN + pg] = acc[r];
    }
}

// ---------------- deformable conv (one dilation per grid.z) ----------------
__device__ __forceinline__ void deform_og(
    int og, int py, int px, int p, int dil, int lane8,
    const float* __restrict__ offp, const float* __restrict__ mskp,
    const float* __restrict__ qb, const float* wsh,
    float& a0, float& a1, float& a2, int rbase) {
    int cb = og * 32 + lane8 * 4;
    int cgrp = (og & 3) * 32 + lane8 * 4;
#pragma unroll
    for (int tap = 0; tap < 9; tap++) {
        float dy = __ldg(&offp[(size_t)(og * 18 + tap * 2) * HWN + p]);
        float dx = __ldg(&offp[(size_t)(og * 18 + tap * 2 + 1) * HWN + p]);
        float m  = __ldg(&mskp[(size_t)(og * 9 + tap) * HWN + p]);
        float fy = (float)(py + (tap / 3) * dil - dil) + dy;
        float fx = (float)(px + (tap % 3) * dil - dil) + dx;
        float y0f = floorf(fy), x0f = floorf(fx);
        float wy = fy - y0f, wx = fx - x0f;
        int y0 = (int)y0f, x0 = (int)x0f;
        float w00 = (1.f - wy) * (1.f - wx) * m;
        float w01 = (1.f - wy) * wx * m;
        float w10 = wy * (1.f - wx) * m;
        float w11 = wy * wx * m;
        bool y0v = (unsigned)y0 < 96u, y1v = (unsigned)(y0 + 1) < 96u;
        bool x0v = (unsigned)x0 < 96u, x1v = (unsigned)(x0 + 1) < 96u;
        float vx = 0.f, vy = 0.f, vz = 0.f, vw = 0.f;
        if (y0v && x0v) {
            float4 t = *(const float4*)&qb[(size_t)(y0 * 96 + x0) * 256 + cb];
            vx += w00 * t.x; vy += w00 * t.y; vz += w00 * t.z; vw += w00 * t.w;
        }
        if (y0v && x1v) {
            float4 t = *(const float4*)&qb[(size_t)(y0 * 96 + x0 + 1) * 256 + cb];
            vx += w01 * t.x; vy += w01 * t.y; vz += w01 * t.z; vw += w01 * t.w;
        }
        if (y1v && x0v) {
            float4 t = *(const float4*)&qb[(size_t)((y0 + 1) * 96 + x0) * 256 + cb];
            vx += w10 * t.x; vy += w10 * t.y; vz += w10 * t.z; vw += w10 * t.w;
        }
        if (y1v && x1v) {
            float4 t = *(const float4*)&qb[(size_t)((y0 + 1) * 96 + x0 + 1) * 256 + cb];
            vx += w11 * t.x; vy += w11 * t.y; vz += w11 * t.z; vw += w11 * t.w;
        }
        {
            float4 w0 = *(const float4*)&wsh[((rbase + 0) * 9 + tap) * 128 + cgrp];
            a0 += vx * w0.x + vy * w0.y + vz * w0.z + vw * w0.w;
        }
        {
            float4 w1 = *(const float4*)&wsh[((rbase + 1) * 9 + tap) * 128 + cgrp];
            a1 += vx * w1.x + vy * w1.y + vz * w1.z + vw * w1.w;
        }
        {
            float4 w2 = *(const float4*)&wsh[((rbase + 2) * 9 + tap) * 128 + cgrp];
            a2 += vx * w2.x + vy * w2.y + vz * w2.z + vw * w2.w;
        }
    }
}

__global__ void deform_kernel() {
    __shared__ __align__(16) float wsh[6 * 9 * 128];
    int z = blockIdx.z;
    int b = z / 3, dz = z - b * 3;
    int dil = 1 << dz;
    int tid = threadIdx.x;
    int lane8 = tid & 7, pl = tid >> 3;
    int px = blockIdx.x * 8 + (pl & 7);
    int py = blockIdx.y * 4 + (pl >> 3);
    int p = py * 96 + px;
    for (int i = tid; i < 6912; i += 256) {
        int r = i / 1152;
        int rem = i - r * 1152;
        int tap = rem >> 7;
        int cg = rem & 127;
        int ex = r >> 1, half = r & 1;
        wsh[i] = g_sW[((size_t)(b * 3 + ex) * 256 + half * 128 + cg) * 9 + tap];
    }
    __syncthreads();
    const float* offp = g_conv + (size_t)(b * NOUT + dz * 216) * HWN;
    const float* mskp = offp + (size_t)144 * HWN;
    const float* qb = g_qhwc + (size_t)b * HWN * CN;
    float a0 = 0.f, a1 = 0.f, a2 = 0.f, a3 = 0.f, a4 = 0.f, a5 = 0.f;
#pragma unroll 1
    for (int og = 0; og < 4; og++)
        deform_og(og, py, px, p, dil, lane8, offp, mskp, qb, wsh, a0, a1, a2, 0);
#pragma unroll 1
    for (int og = 4; og < 8; og++)
        deform_og(og, py, px, p, dil, lane8, offp, mskp, qb, wsh, a3, a4, a5, 3);
    float acc[6] = {a0, a1, a2, a3, a4, a5};
#pragma unroll
    for (int r = 0; r < 6; r++) {
        acc[r] += __shfl_xor_sync(0xffffffffu, acc[r], 1);
        acc[r] += __shfl_xor_sync(0xffffffffu, acc[r], 2);
        acc[r] += __shfl_xor_sync(0xffffffffu, acc[r], 4);
    }
    if (lane8 == 0) {
        size_t obase = ((size_t)b * 24 + 6 + dz * 6) * HWN + p;
#pragma unroll
        for (int r = 0; r < 6; r++) g_sim[obase + (size_t)r * HWN] = acc[r];
    }
}

// ---------------- final 1x1 conv 24 -> 256 ----------------
__global__ void outconv_kernel(const float* __restrict__ ow, const float* __restrict__ ob,
                               float* __restrict__ out) {
    __shared__ float ws[256 * 25];
    __shared__ float st[24 * 65];
    int b = blockIdx.y;
    int m0 = blockIdx.x * 64;
    int tid = threadIdx.x;
    for (int i = tid; i < 6144; i += 256) {
        int oc = i / 24, k = i - oc * 24;
        ws[oc * 25 + k] = ow[i];
    }
    for (int i = tid; i < 24 * 64; i += 256) {
        int ch = i >> 6, j = i & 63;
        st[ch * 65 + j] = g_sim[((size_t)b * 24 + ch) * HWN + m0 + j];
    }
    __syncthreads();
    int j = tid & 63;
    int ocb = (tid >> 6) * 64;
    for (int oc = ocb; oc < ocb + 64; oc++) {
        float a = ob[oc];
#pragma unroll
        for (int k = 0; k < 24; k++) a += ws[oc * 25 + k] * st[k * 65 + j];
        out[((size_t)b * 256 + oc) * HWN + m0 + j] = a;
    }
}

// ---------------- launch ----------------
extern "C" void kernel_launch(void* const* d_in, const int* in_sizes, int n_in,
                              void* d_out, int out_size) {
    const float* qf    = (const float*)d_in[0];
    const float* sf    = (const float*)d_in[1];
    const float* in_w  = (const float*)d_in[2];
    const float* in_b  = (const float*)d_in[3];
    const float* ln_g  = (const float*)d_in[4];
    const float* ln_b  = (const float*)d_in[5];
    const float* out_w = (const float*)d_in[6];
    const float* out_b = (const float*)d_in[7];
    const float* offw1 = (const float*)d_in[8];
    const float* offb1 = (const float*)d_in[9];
    const float* mskw1 = (const float*)d_in[10];
    const float* mskb1 = (const float*)d_in[11];
    const float* offw2 = (const float*)d_in[12];
    const float* offb2 = (const float*)d_in[13];
    const float* mskw2 = (const float*)d_in[14];
    const float* mskb2 = (const float*)d_in[15];
    const float* offw4 = (const float*)d_in[16];
    const float* offb4 = (const float*)d_in[17];
    const float* mskw4 = (const float*)d_in[18];
    const float* mskb4 = (const float*)d_in[19];
    float* out = (float*)d_out;

    pack_wa<<<256, 256>>>(in_w);
    pack_big<<<(KBIG * NPAD + 255) / 256, 256>>>(offw1, mskw1, offw2, mskw2, offw4, mskw4,
                                                 offb1, mskb1, offb2, mskb2, offb4, mskb4);
    gemm_in<<<dim3(72, 4, 2), 256>>>(qf, in_b);
    support_kernel<<<6, 256>>>(sf, in_b, ln_g, ln_b);
    ln_kernel<<<576, 256>>>(ln_g, ln_b);
    gemm_big<<<dim3(72, 11, 2), 256>>>();
    softmax_kernel<<<dim3(36, 3, 2), 256>>>();
    sim0_kernel<<<dim3(288, 2), 256>>>();
    deform_kernel<<<dim3(12, 24, 6), 256>>>();
    outconv_kernel<<<dim3(144, 2), 256>>>(out_w, out_b, out);
}